// round 5
// baseline (speedup 1.0000x reference)
#include <cuda_runtime.h>
#include <cstdint>

#define N_NODES   50000
#define N_EDGES   800000
#define F         96
#define N_CLASSES 10
#define N_GRAPHS  512
#define NF        (N_NODES * F)

// ---------------- scratch (device globals; no allocations allowed) ----------------
__device__ float g_deg[N_NODES];
__device__ float g_dis[N_NODES];
__device__ float g_selfn[N_NODES];
__device__ int   g_src[N_EDGES];
__device__ int   g_dst[N_EDGES];
__device__ __align__(16) float g_norm[N_EDGES];
__device__ __align__(16) float g_xw[NF];
__device__ __align__(16) float g_hA[NF];
__device__ __align__(16) float g_hB[NF];
__device__ float g_pool[N_GRAPHS * F];
__device__ int   g_cnt[N_GRAPHS];
__device__ int   g_ei64;     // 1 if edge_index buffer is int64, 0 if int32
__device__ int   g_b64;      // same for batch

__device__ __forceinline__ float* buf_sel(int s) { return s == 1 ? g_hA : g_hB; }

__device__ __forceinline__ int load_idx(const void* p, long long i, int is64, int lim) {
    long long v = is64 ? ((const long long*)p)[i] : (long long)((const int*)p)[i];
    int r = (int)v;
    if (r < 0) r = 0;
    if (r >= lim) r = lim - 1;
    return r;
}

// ---------------- dtype detection (single thread; ~1us) ----------------------------
__global__ void k_detect(const void* ei, const void* bt) {
    if (threadIdx.x == 0 && blockIdx.x == 0) {
        const unsigned long long* p = (const unsigned long long*)ei;
        int is64 = 1;
        for (int i = 0; i < 512; i++)
            if (p[i] >= (1ULL << 32)) { is64 = 0; break; }
        g_ei64 = is64;
        const unsigned long long* q = (const unsigned long long*)bt;
        int b64 = 1;
        for (int i = 0; i < 512; i++)
            if (q[i] >= (1ULL << 32)) { b64 = 0; break; }
        g_b64 = b64;
    }
}

// ---------------- init: deg=1 (self loop), pool/cnt = 0 ----------------------------
__global__ void k_init() {
    int i = blockIdx.x * blockDim.x + threadIdx.x;
    if (i < N_NODES)       g_deg[i] = 1.0f;
    if (i < N_GRAPHS * F)  g_pool[i] = 0.0f;
    if (i < N_GRAPHS)      g_cnt[i] = 0;
}

// ---------------- edge prep: index decode + weighted degree ------------------------
__global__ void k_prep(const void* __restrict__ ei, const float* __restrict__ w) {
    int e = blockIdx.x * blockDim.x + threadIdx.x;
    if (e >= N_EDGES) return;
    int is64 = g_ei64;
    int s = load_idx(ei, e, is64, N_NODES);
    int d = load_idx(ei, (long long)N_EDGES + e, is64, N_NODES);
    g_src[e] = s;
    g_dst[e] = d;
    atomicAdd(&g_deg[d], w[e]);
}

__global__ void k_dis() {
    int i = blockIdx.x * blockDim.x + threadIdx.x;
    if (i >= N_NODES) return;
    float dg  = g_deg[i];
    float dis = dg > 0.0f ? rsqrtf(dg) : 0.0f;
    g_dis[i]   = dis;
    g_selfn[i] = dis * dis;
}

__global__ void k_norm(const float* __restrict__ w) {
    int e = blockIdx.x * blockDim.x + threadIdx.x;
    if (e >= N_EDGES) return;
    g_norm[e] = g_dis[g_src[e]] * w[e] * g_dis[g_dst[e]];
}

// ---------------- GEMM: C[50000,96] = A[50000,96] @ W[96,96] -> g_xw ---------------
__global__ void k_gemm(const float* __restrict__ Aext, int asel,
                       const float* __restrict__ W) {
    __shared__ float ws[96 * 96];     // 36864 B
    __shared__ __align__(16) float xs[24 * 96];     //  9216 B
    const float* A = (asel == 0) ? Aext : (asel == 1 ? g_hA : g_hB);
    float* C = g_xw;

    int tid = threadIdx.x;
    for (int idx = tid; idx < 96 * 96; idx += 256) ws[idx] = W[idx];

    int r0 = blockIdx.x * 24;
    const float4* A4 = (const float4*)A;
    float4* xs4 = (float4*)xs;
    for (int idx = tid; idx < 24 * 24; idx += 256) {
        int r = idx / 24;
        float4 v = make_float4(0.f, 0.f, 0.f, 0.f);
        if (r0 + r < N_NODES) v = A4[(size_t)r0 * 24 + idx];
        xs4[idx] = v;
    }
    __syncthreads();

    if (tid < 192) {
        int tx = tid & 31;          // 32 col-groups of 3 cols
        int wy = tid >> 5;          // 6 row-groups of 4 rows
        int rb = wy * 4;
        int c0 = tx * 3;

        float acc[4][3];
#pragma unroll
        for (int r = 0; r < 4; r++)
#pragma unroll
            for (int j = 0; j < 3; j++) acc[r][j] = 0.0f;

#pragma unroll 4
        for (int kk = 0; kk < 96; kk += 4) {
            float4 xv[4];
#pragma unroll
            for (int r = 0; r < 4; r++)
                xv[r] = *(const float4*)&xs[(rb + r) * 96 + kk];
            float wv[4][3];
#pragma unroll
            for (int q = 0; q < 4; q++)
#pragma unroll
                for (int j = 0; j < 3; j++)
                    wv[q][j] = ws[(kk + q) * 96 + c0 + j];
#pragma unroll
            for (int r = 0; r < 4; r++) {
#pragma unroll
                for (int j = 0; j < 3; j++) {
                    acc[r][j] = fmaf(xv[r].x, wv[0][j], acc[r][j]);
                    acc[r][j] = fmaf(xv[r].y, wv[1][j], acc[r][j]);
                    acc[r][j] = fmaf(xv[r].z, wv[2][j], acc[r][j]);
                    acc[r][j] = fmaf(xv[r].w, wv[3][j], acc[r][j]);
                }
            }
        }

#pragma unroll
        for (int r = 0; r < 4; r++) {
            int row = r0 + rb + r;
            if (row < N_NODES) {
#pragma unroll
                for (int j = 0; j < 3; j++)
                    C[(size_t)row * 96 + c0 + j] = acc[r][j];
            }
        }
    }
}

// ---------------- aggregation: out = selfn * xw (init) -----------------------------
__global__ void k_selfinit(int osel) {
    int i = blockIdx.x * blockDim.x + threadIdx.x;
    if (i >= NF / 4) return;
    float* out = buf_sel(osel);
    int node = i / 24;
    float s = g_selfn[node];
    float4 v = ((const float4*)g_xw)[i];
    v.x *= s; v.y *= s; v.z *= s; v.w *= s;
    ((float4*)out)[i] = v;
}

// ---------------- aggregation: edge scatter, scalar float atomics ------------------
__global__ void k_scatter(int osel) {
    int i = blockIdx.x * blockDim.x + threadIdx.x;
    if (i >= N_EDGES * 24) return;
    float* out = buf_sel(osel);
    int e = i / 24;
    int g = i - e * 24;
    float nv = g_norm[e];
    int s = g_src[e], d = g_dst[e];
    float4 v = ((const float4*)g_xw)[(size_t)s * 24 + g];
    float* p = out + (size_t)d * 96 + g * 4;
    atomicAdd(p + 0, v.x * nv);
    atomicAdd(p + 1, v.y * nv);
    atomicAdd(p + 2, v.z * nv);
    atomicAdd(p + 3, v.w * nv);
}

// ---------------- bias (+ optional relu), in place ---------------------------------
__global__ void k_bias(int osel, const float* __restrict__ b, int relu) {
    int i = blockIdx.x * blockDim.x + threadIdx.x;
    if (i >= NF) return;
    float* h = buf_sel(osel);
    int f = i % 96;
    float v = h[i] + b[f];
    if (relu) v = fmaxf(v, 0.0f);
    h[i] = v;
}

// ---------------- global mean pool (sums + counts), reads g_hA ---------------------
__global__ void k_pool(const void* __restrict__ batch) {
    int i = blockIdx.x * blockDim.x + threadIdx.x;
    int b64 = g_b64;
    if (i < NF) {
        int node = i / 96;
        int f = i - node * 96;
        int gph = load_idx(batch, node, b64, N_GRAPHS);
        atomicAdd(&g_pool[gph * 96 + f], g_hA[i]);
    }
    if (i < N_NODES) {
        int gph = load_idx(batch, i, b64, N_GRAPHS);
        atomicAdd(&g_cnt[gph], 1);
    }
}

// ---------------- head: out[g,c] = (pool[g,:]/cnt) @ Wl + bl -----------------------
__global__ void k_final(const float* __restrict__ Wl, const float* __restrict__ bl,
                        float* __restrict__ out) {
    int t = blockIdx.x * blockDim.x + threadIdx.x;
    if (t >= N_GRAPHS * N_CLASSES) return;
    int gph = t / N_CLASSES;
    int c = t - gph * N_CLASSES;
    float inv = 1.0f / fmaxf((float)g_cnt[gph], 1.0f);
    float s = 0.0f;
#pragma unroll 8
    for (int k = 0; k < 96; k++)
        s = fmaf(g_pool[gph * 96 + k], Wl[k * N_CLASSES + c], s);
    out[t] = s * inv + bl[c];
}

// ===================================================================================
extern "C" void kernel_launch(void* const* d_in, const int* in_sizes, int n_in,
                              void* d_out, int out_size) {
    // Identify inputs by element count; fall back to positional order.
    int ix = 0, iew = 1, iWl = 8, ibl = 9, iei = 10, ibatch = 11;
    int iW[3] = {2, 4, 6}, iB[3] = {3, 5, 7};
    {
        int tW[3], tB[3], nw = 0, nb = 0;
        int tx = -1, tew = -1, twl = -1, tbl = -1, tei = -1, tbt = -1;
        for (int i = 0; i < n_in; i++) {
            switch (in_sizes[i]) {
                case N_NODES * F:      tx  = i; break;   // 4800000
                case N_EDGES:          tew = i; break;   // 800000
                case F * F:            if (nw < 3) tW[nw++] = i; break;  // 9216
                case F:                if (nb < 3) tB[nb++] = i; break;  // 96
                case F * N_CLASSES:    twl = i; break;   // 960
                case N_CLASSES:        tbl = i; break;   // 10
                case 2 * N_EDGES:      tei = i; break;   // 1600000
                case N_NODES:          tbt = i; break;   // 50000
                default: break;
            }
        }
        if (tx >= 0 && tew >= 0 && nw == 3 && nb == 3 && twl >= 0 && tbl >= 0 &&
            tei >= 0 && tbt >= 0) {
            ix = tx; iew = tew; iWl = twl; ibl = tbl; iei = tei; ibatch = tbt;
            for (int j = 0; j < 3; j++) { iW[j] = tW[j]; iB[j] = tB[j]; }
        }
    }

    const float* x     = (const float*)d_in[ix];
    const float* ew    = (const float*)d_in[iew];
    const float* W1    = (const float*)d_in[iW[0]];
    const float* b1    = (const float*)d_in[iB[0]];
    const float* W2    = (const float*)d_in[iW[1]];
    const float* b2    = (const float*)d_in[iB[1]];
    const float* W3    = (const float*)d_in[iW[2]];
    const float* b3    = (const float*)d_in[iB[2]];
    const float* Wl    = (const float*)d_in[iWl];
    const float* bl    = (const float*)d_in[ibl];
    const void*  ei    = d_in[iei];
    const void*  batch = d_in[ibatch];
    float* out = (float*)d_out;

    const int T = 256;

    // ---- dtype detection + graph normalization (shared by all 3 layers) ----
    k_detect<<<1, 32>>>(ei, batch);
    k_init<<<(N_NODES + T - 1) / T, T>>>();
    k_prep<<<(N_EDGES + T - 1) / T, T>>>(ei, ew);
    k_dis <<<(N_NODES + T - 1) / T, T>>>();
    k_norm<<<(N_EDGES + T - 1) / T, T>>>(ew);

    const int gemm_grid    = (N_NODES + 23) / 24;
    const int self_grid    = (NF / 4 + T - 1) / T;
    const int scatter_grid = (N_EDGES * 24 + T - 1) / T;
    const int nf_grid      = (NF + T - 1) / T;

    // ---- layer 1: x -> hA (relu) ----
    k_gemm<<<gemm_grid, T>>>(x, 0, W1);
    k_selfinit<<<self_grid, T>>>(1);
    k_scatter<<<scatter_grid, T>>>(1);
    k_bias<<<nf_grid, T>>>(1, b1, 1);

    // ---- layer 2: hA -> hB (relu) ----
    k_gemm<<<gemm_grid, T>>>(nullptr, 1, W2);
    k_selfinit<<<self_grid, T>>>(2);
    k_scatter<<<scatter_grid, T>>>(2);
    k_bias<<<nf_grid, T>>>(2, b2, 1);

    // ---- layer 3: hB -> hA (no relu) ----
    k_gemm<<<gemm_grid, T>>>(nullptr, 2, W3);
    k_selfinit<<<self_grid, T>>>(1);
    k_scatter<<<scatter_grid, T>>>(1);
    k_bias<<<nf_grid, T>>>(1, b3, 0);

    // ---- pool + head ----
    k_pool<<<nf_grid, T>>>(batch);
    k_final<<<(N_GRAPHS * N_CLASSES + T - 1) / T, T>>>(Wl, bl, out);
}

// round 7
// speedup vs baseline: 2.4818x; 2.4818x over previous
#include <cuda_runtime.h>
#include <cstdint>

#define N_NODES   50000
#define N_EDGES   800000
#define F         96
#define NF4       (F / 4)          // 24 float4 per node row
#define N_CLASSES 10
#define N_GRAPHS  512
#define NF        (N_NODES * F)
#define SCAN_NB   ((N_NODES + 255) / 256)   // 196

// ---------------- scratch (device globals; no allocations allowed) ----------------
__device__ float g_deg[N_NODES];
__device__ float g_dis[N_NODES];
__device__ float g_selfn[N_NODES];
__device__ int   g_gph[N_NODES];            // decoded batch id per node
__device__ int   g_cntd[N_NODES];           // per-dst edge count
__device__ int   g_cur[N_NODES];            // fill cursor
__device__ int   g_off[N_NODES + 1];        // CSR offsets (exclusive)
__device__ int   g_part[256];               // scan partials
__device__ int   g_partx[256];
__device__ int   g_csr_src[N_EDGES];
__device__ __align__(16) float g_csr_norm[N_EDGES];
__device__ __align__(16) float g_xw[NF];
__device__ __align__(16) float g_hA[NF];
__device__ __align__(16) float g_hB[NF];
__device__ float g_pool[N_GRAPHS * F];
__device__ int   g_cnt[N_GRAPHS];
__device__ int   g_ei64, g_b64;

__device__ __forceinline__ float* buf_sel(int s) { return s == 1 ? g_hA : g_hB; }

__device__ __forceinline__ int load_idx(const void* p, long long i, int is64, int lim) {
    long long v = is64 ? ((const long long*)p)[i] : (long long)((const int*)p)[i];
    int r = (int)v;
    if (r < 0) r = 0;
    if (r >= lim) r = lim - 1;
    return r;
}

// ---------------- dtype detection -------------------------------------------------
__global__ void k_detect(const void* ei, const void* bt) {
    if (threadIdx.x == 0 && blockIdx.x == 0) {
        const unsigned long long* p = (const unsigned long long*)ei;
        int is64 = 1;
        for (int i = 0; i < 512; i++)
            if (p[i] >= (1ULL << 32)) { is64 = 0; break; }
        g_ei64 = is64;
        const unsigned long long* q = (const unsigned long long*)bt;
        int b64 = 1;
        for (int i = 0; i < 512; i++)
            if (q[i] >= (1ULL << 32)) { b64 = 0; break; }
        g_b64 = b64;
    }
}

// ---------------- init ------------------------------------------------------------
__global__ void k_init() {
    int i = blockIdx.x * blockDim.x + threadIdx.x;
    if (i < N_NODES) { g_deg[i] = 1.0f; g_cntd[i] = 0; g_cur[i] = 0; }
    if (i < N_GRAPHS * F)  g_pool[i] = 0.0f;
    if (i < N_GRAPHS)      g_cnt[i] = 0;
}

// ---------------- prep: weighted degree + dst counts ------------------------------
__global__ void k_prep(const void* __restrict__ ei, const float* __restrict__ w) {
    int e = blockIdx.x * blockDim.x + threadIdx.x;
    if (e >= N_EDGES) return;
    int is64 = g_ei64;
    int d = load_idx(ei, (long long)N_EDGES + e, is64, N_NODES);
    atomicAdd(&g_deg[d], w[e]);
    atomicAdd(&g_cntd[d], 1);
}

// ---------------- dis + selfn + batch decode + graph counts ------------------------
__global__ void k_dis(const void* __restrict__ batch) {
    int i = blockIdx.x * blockDim.x + threadIdx.x;
    if (i >= N_NODES) return;
    float dg  = g_deg[i];
    float dis = dg > 0.0f ? rsqrtf(dg) : 0.0f;
    g_dis[i]   = dis;
    g_selfn[i] = dis * dis;
    int gph = load_idx(batch, i, g_b64, N_GRAPHS);
    g_gph[i] = gph;
    atomicAdd(&g_cnt[gph], 1);
}

// ---------------- scan: block-local exclusive scan of counts -----------------------
__global__ void k_scan1() {
    __shared__ int sm[256];
    int b = blockIdx.x, t = threadIdx.x;
    int i = b * 256 + t;
    int v = (i < N_NODES) ? g_cntd[i] : 0;
    sm[t] = v; __syncthreads();
    for (int ofs = 1; ofs < 256; ofs <<= 1) {
        int add = (t >= ofs) ? sm[t - ofs] : 0;
        __syncthreads();
        sm[t] += add;
        __syncthreads();
    }
    if (i < N_NODES) g_off[i] = sm[t] - v;
    if (t == 255) g_part[b] = sm[255];
}

__global__ void k_scan2() {
    __shared__ int sm[256];
    int t = threadIdx.x;
    int v = (t < SCAN_NB) ? g_part[t] : 0;
    sm[t] = v; __syncthreads();
    for (int ofs = 1; ofs < 256; ofs <<= 1) {
        int add = (t >= ofs) ? sm[t - ofs] : 0;
        __syncthreads();
        sm[t] += add;
        __syncthreads();
    }
    g_partx[t] = sm[t] - v;
}

__global__ void k_scan3() {
    int i = blockIdx.x * 256 + threadIdx.x;
    if (i < N_NODES) g_off[i] += g_partx[blockIdx.x];
    if (i == 0) g_off[N_NODES] = N_EDGES;
}

// ---------------- fill CSR (src + norm, sorted by dst) -----------------------------
__global__ void k_fill(const void* __restrict__ ei, const float* __restrict__ w) {
    int e = blockIdx.x * blockDim.x + threadIdx.x;
    if (e >= N_EDGES) return;
    int is64 = g_ei64;
    int s = load_idx(ei, e, is64, N_NODES);
    int d = load_idx(ei, (long long)N_EDGES + e, is64, N_NODES);
    int slot = g_off[d] + atomicAdd(&g_cur[d], 1);
    g_csr_src[slot]  = s;
    g_csr_norm[slot] = g_dis[s] * w[e] * g_dis[d];
}

// ---------------- GEMM: C[50000,96] = A @ W[96,96] -> g_xw -------------------------
__global__ void k_gemm(const float* __restrict__ Aext, int asel,
                       const float* __restrict__ W) {
    __shared__ float ws[96 * 96];
    __shared__ __align__(16) float xs[24 * 96];
    const float* A = (asel == 0) ? Aext : (asel == 1 ? g_hA : g_hB);
    float* C = g_xw;

    int tid = threadIdx.x;
    for (int idx = tid; idx < 96 * 96; idx += 256) ws[idx] = W[idx];

    int r0 = blockIdx.x * 24;
    const float4* A4 = (const float4*)A;
    float4* xs4 = (float4*)xs;
    for (int idx = tid; idx < 24 * 24; idx += 256) {
        int r = idx / 24;
        float4 v = make_float4(0.f, 0.f, 0.f, 0.f);
        if (r0 + r < N_NODES) v = A4[(size_t)r0 * 24 + idx];
        xs4[idx] = v;
    }
    __syncthreads();

    if (tid < 192) {
        int tx = tid & 31, wy = tid >> 5;
        int rb = wy * 4, c0 = tx * 3;
        float acc[4][3];
#pragma unroll
        for (int r = 0; r < 4; r++)
#pragma unroll
            for (int j = 0; j < 3; j++) acc[r][j] = 0.0f;

#pragma unroll 4
        for (int kk = 0; kk < 96; kk += 4) {
            float4 xv[4];
#pragma unroll
            for (int r = 0; r < 4; r++)
                xv[r] = *(const float4*)&xs[(rb + r) * 96 + kk];
            float wv[4][3];
#pragma unroll
            for (int q = 0; q < 4; q++)
#pragma unroll
                for (int j = 0; j < 3; j++)
                    wv[q][j] = ws[(kk + q) * 96 + c0 + j];
#pragma unroll
            for (int r = 0; r < 4; r++)
#pragma unroll
                for (int j = 0; j < 3; j++) {
                    acc[r][j] = fmaf(xv[r].x, wv[0][j], acc[r][j]);
                    acc[r][j] = fmaf(xv[r].y, wv[1][j], acc[r][j]);
                    acc[r][j] = fmaf(xv[r].z, wv[2][j], acc[r][j]);
                    acc[r][j] = fmaf(xv[r].w, wv[3][j], acc[r][j]);
                }
        }
#pragma unroll
        for (int r = 0; r < 4; r++) {
            int row = r0 + rb + r;
            if (row < N_NODES)
#pragma unroll
                for (int j = 0; j < 3; j++)
                    C[(size_t)row * 96 + c0 + j] = acc[r][j];
        }
    }
}

// ---------------- fused gather: CSR aggregate + self-loop + bias (+relu) (+pool) ---
// One warp per node. Lanes 0..23 each own one float4 of the 96-float row.
__global__ void k_gather(int osel, const float* __restrict__ b, int relu, int do_pool) {
    int warp = (blockIdx.x * blockDim.x + threadIdx.x) >> 5;
    int lane = threadIdx.x & 31;
    if (warp >= N_NODES || lane >= NF4) return;
    float* out = buf_sel(osel);
    const float4* xw4 = (const float4*)g_xw;

    int beg = __ldg(&g_off[warp]), end = __ldg(&g_off[warp + 1]);
    float4 acc = make_float4(0.f, 0.f, 0.f, 0.f);
    int i = beg;
    // 2x unrolled edge loop
    for (; i + 1 < end; i += 2) {
        int   s0 = __ldg(&g_csr_src[i]),  s1 = __ldg(&g_csr_src[i + 1]);
        float n0 = __ldg(&g_csr_norm[i]), n1 = __ldg(&g_csr_norm[i + 1]);
        float4 v0 = xw4[(size_t)s0 * NF4 + lane];
        float4 v1 = xw4[(size_t)s1 * NF4 + lane];
        acc.x = fmaf(n0, v0.x, acc.x); acc.y = fmaf(n0, v0.y, acc.y);
        acc.z = fmaf(n0, v0.z, acc.z); acc.w = fmaf(n0, v0.w, acc.w);
        acc.x = fmaf(n1, v1.x, acc.x); acc.y = fmaf(n1, v1.y, acc.y);
        acc.z = fmaf(n1, v1.z, acc.z); acc.w = fmaf(n1, v1.w, acc.w);
    }
    if (i < end) {
        int   s0 = __ldg(&g_csr_src[i]);
        float n0 = __ldg(&g_csr_norm[i]);
        float4 v0 = xw4[(size_t)s0 * NF4 + lane];
        acc.x = fmaf(n0, v0.x, acc.x); acc.y = fmaf(n0, v0.y, acc.y);
        acc.z = fmaf(n0, v0.z, acc.z); acc.w = fmaf(n0, v0.w, acc.w);
    }
    // self loop
    {
        float sn = g_selfn[warp];
        float4 v = xw4[(size_t)warp * NF4 + lane];
        acc.x = fmaf(sn, v.x, acc.x); acc.y = fmaf(sn, v.y, acc.y);
        acc.z = fmaf(sn, v.z, acc.z); acc.w = fmaf(sn, v.w, acc.w);
    }
    // bias + relu
    float4 bv = ((const float4*)b)[lane];
    acc.x += bv.x; acc.y += bv.y; acc.z += bv.z; acc.w += bv.w;
    if (relu) {
        acc.x = fmaxf(acc.x, 0.f); acc.y = fmaxf(acc.y, 0.f);
        acc.z = fmaxf(acc.z, 0.f); acc.w = fmaxf(acc.w, 0.f);
    }
    ((float4*)out)[(size_t)warp * NF4 + lane] = acc;

    if (do_pool) {
        int gph = g_gph[warp];
        float* pp = &g_pool[gph * F + lane * 4];
        atomicAdd(pp + 0, acc.x);
        atomicAdd(pp + 1, acc.y);
        atomicAdd(pp + 2, acc.z);
        atomicAdd(pp + 3, acc.w);
    }
}

// ---------------- head: out[g,c] = (pool[g,:]/cnt) @ Wl + bl -----------------------
__global__ void k_final(const float* __restrict__ Wl, const float* __restrict__ bl,
                        float* __restrict__ out) {
    int t = blockIdx.x * blockDim.x + threadIdx.x;
    if (t >= N_GRAPHS * N_CLASSES) return;
    int gph = t / N_CLASSES;
    int c = t - gph * N_CLASSES;
    float inv = 1.0f / fmaxf((float)g_cnt[gph], 1.0f);
    float s = 0.0f;
#pragma unroll 8
    for (int k = 0; k < 96; k++)
        s = fmaf(g_pool[gph * 96 + k], Wl[k * N_CLASSES + c], s);
    out[t] = s * inv + bl[c];
}

// ===================================================================================
extern "C" void kernel_launch(void* const* d_in, const int* in_sizes, int n_in,
                              void* d_out, int out_size) {
    // Identify inputs by element count; fall back to positional order.
    int ix = 0, iew = 1, iWl = 8, ibl = 9, iei = 10, ibatch = 11;
    int iW[3] = {2, 4, 6}, iB[3] = {3, 5, 7};
    {
        int tW[3], tB[3], nw = 0, nb = 0;
        int tx = -1, tew = -1, twl = -1, tbl = -1, tei = -1, tbt = -1;
        for (int i = 0; i < n_in; i++) {
            switch (in_sizes[i]) {
                case N_NODES * F:      tx  = i; break;
                case N_EDGES:          tew = i; break;
                case F * F:            if (nw < 3) tW[nw++] = i; break;
                case F:                if (nb < 3) tB[nb++] = i; break;
                case F * N_CLASSES:    twl = i; break;
                case N_CLASSES:        tbl = i; break;
                case 2 * N_EDGES:      tei = i; break;
                case N_NODES:          tbt = i; break;
                default: break;
            }
        }
        if (tx >= 0 && tew >= 0 && nw == 3 && nb == 3 && twl >= 0 && tbl >= 0 &&
            tei >= 0 && tbt >= 0) {
            ix = tx; iew = tew; iWl = twl; ibl = tbl; iei = tei; ibatch = tbt;
            for (int j = 0; j < 3; j++) { iW[j] = tW[j]; iB[j] = tB[j]; }
        }
    }

    const float* x     = (const float*)d_in[ix];
    const float* ew    = (const float*)d_in[iew];
    const float* W1    = (const float*)d_in[iW[0]];
    const float* b1    = (const float*)d_in[iB[0]];
    const float* W2    = (const float*)d_in[iW[1]];
    const float* b2    = (const float*)d_in[iB[1]];
    const float* W3    = (const float*)d_in[iW[2]];
    const float* b3    = (const float*)d_in[iB[2]];
    const float* Wl    = (const float*)d_in[iWl];
    const float* bl    = (const float*)d_in[ibl];
    const void*  ei    = d_in[iei];
    const void*  batch = d_in[ibatch];
    float* out = (float*)d_out;

    const int T = 256;
    const int node_grid = (N_NODES + T - 1) / T;
    const int edge_grid = (N_EDGES + T - 1) / T;

    // ---- prep: dtype detect, CSR build, normalization (shared by 3 layers) ----
    k_detect<<<1, 32>>>(ei, batch);
    k_init<<<node_grid, T>>>();
    k_prep<<<edge_grid, T>>>(ei, ew);
    k_dis<<<node_grid, T>>>(batch);
    k_scan1<<<SCAN_NB, 256>>>();
    k_scan2<<<1, 256>>>();
    k_scan3<<<SCAN_NB, 256>>>();
    k_fill<<<edge_grid, T>>>(ei, ew);

    const int gemm_grid   = (N_NODES + 23) / 24;
    const int gather_grid = (N_NODES * 32 + T - 1) / T;   // one warp per node

    // ---- layer 1: x -> hA (relu) ----
    k_gemm<<<gemm_grid, T>>>(x, 0, W1);
    k_gather<<<gather_grid, T>>>(1, b1, 1, 0);

    // ---- layer 2: hA -> hB (relu) ----
    k_gemm<<<gemm_grid, T>>>(nullptr, 1, W2);
    k_gather<<<gather_grid, T>>>(2, b2, 1, 0);

    // ---- layer 3: hB -> hA (no relu) + fused mean-pool accumulation ----
    k_gemm<<<gemm_grid, T>>>(nullptr, 2, W3);
    k_gather<<<gather_grid, T>>>(1, b3, 0, 1);

    // ---- head ----
    k_final<<<(N_GRAPHS * N_CLASSES + T - 1) / T, T>>>(Wl, bl, out);
}

// round 8
// speedup vs baseline: 2.5141x; 1.0130x over previous
#include <cuda_runtime.h>
#include <cstdint>

#define N_NODES   50000
#define N_EDGES   800000
#define F         96
#define NF4       (F / 4)          // 24 float4 per node row
#define N_CLASSES 10
#define N_GRAPHS  512
#define NF        (N_NODES * F)
#define SCAN_NB   ((N_NODES + 255) / 256)   // 196

// ---------------- scratch (device globals; no allocations allowed) ----------------
__device__ float g_deg[N_NODES];
__device__ float g_dis[N_NODES];
__device__ float g_selfn[N_NODES];
__device__ int   g_gph[N_NODES];            // decoded batch id per node
__device__ int   g_cntd[N_NODES];           // per-dst edge count
__device__ int   g_cur[N_NODES];            // fill cursor
__device__ int   g_off[N_NODES + 1];        // CSR offsets (exclusive)
__device__ int   g_part[256];               // scan partials
__device__ int   g_partx[256];
__device__ int   g_csr_src[N_EDGES];
__device__ __align__(16) float g_csr_norm[N_EDGES];
__device__ __align__(16) float g_xw[NF];
__device__ __align__(16) float g_hA[NF];
__device__ __align__(16) float g_hB[NF];
__device__ float g_pool[N_GRAPHS * F];
__device__ int   g_cnt[N_GRAPHS];
__device__ int   g_ei64, g_b64;

__device__ __forceinline__ float* buf_sel(int s) { return s == 1 ? g_hA : g_hB; }

__device__ __forceinline__ int load_idx(const void* p, long long i, int is64, int lim) {
    long long v = is64 ? ((const long long*)p)[i] : (long long)((const int*)p)[i];
    int r = (int)v;
    if (r < 0) r = 0;
    if (r >= lim) r = lim - 1;
    return r;
}

// ---------------- init + dtype detection (merged) ----------------------------------
__global__ void k_init(const void* ei, const void* bt) {
    int i = blockIdx.x * blockDim.x + threadIdx.x;
    if (i < N_NODES) { g_deg[i] = 1.0f; g_cntd[i] = 0; g_cur[i] = 0; }
    if (i < N_GRAPHS * F)  g_pool[i] = 0.0f;
    if (i < N_GRAPHS)      g_cnt[i] = 0;
    if (i == 0) {
        const unsigned long long* p = (const unsigned long long*)ei;
        int is64 = 1;
        for (int k = 0; k < 512; k++)
            if (p[k] >= (1ULL << 32)) { is64 = 0; break; }
        g_ei64 = is64;
        const unsigned long long* q = (const unsigned long long*)bt;
        int b64 = 1;
        for (int k = 0; k < 512; k++)
            if (q[k] >= (1ULL << 32)) { b64 = 0; break; }
        g_b64 = b64;
    }
}

// ---------------- prep: weighted degree + dst counts ------------------------------
__global__ void k_prep(const void* __restrict__ ei, const float* __restrict__ w) {
    int e = blockIdx.x * blockDim.x + threadIdx.x;
    if (e >= N_EDGES) return;
    int is64 = g_ei64;
    int d = load_idx(ei, (long long)N_EDGES + e, is64, N_NODES);
    atomicAdd(&g_deg[d], w[e]);
    atomicAdd(&g_cntd[d], 1);
}

// ---------------- scan1 + dis + selfn + batch decode (merged, node-indexed) --------
__global__ void k_scan1(const void* __restrict__ batch) {
    __shared__ int sm[256];
    int b = blockIdx.x, t = threadIdx.x;
    int i = b * 256 + t;

    // dis / selfn / batch decode (independent of scan below)
    if (i < N_NODES) {
        float dg  = g_deg[i];
        float dis = dg > 0.0f ? rsqrtf(dg) : 0.0f;
        g_dis[i]   = dis;
        g_selfn[i] = dis * dis;
        int gph = load_idx(batch, i, g_b64, N_GRAPHS);
        g_gph[i] = gph;
        atomicAdd(&g_cnt[gph], 1);
    }

    // block-local exclusive scan of counts
    int v = (i < N_NODES) ? g_cntd[i] : 0;
    sm[t] = v; __syncthreads();
    for (int ofs = 1; ofs < 256; ofs <<= 1) {
        int add = (t >= ofs) ? sm[t - ofs] : 0;
        __syncthreads();
        sm[t] += add;
        __syncthreads();
    }
    if (i < N_NODES) g_off[i] = sm[t] - v;
    if (t == 255) g_part[b] = sm[255];
}

__global__ void k_scan2() {
    __shared__ int sm[256];
    int t = threadIdx.x;
    int v = (t < SCAN_NB) ? g_part[t] : 0;
    sm[t] = v; __syncthreads();
    for (int ofs = 1; ofs < 256; ofs <<= 1) {
        int add = (t >= ofs) ? sm[t - ofs] : 0;
        __syncthreads();
        sm[t] += add;
        __syncthreads();
    }
    g_partx[t] = sm[t] - v;
}

__global__ void k_scan3() {
    int i = blockIdx.x * 256 + threadIdx.x;
    if (i < N_NODES) g_off[i] += g_partx[blockIdx.x];
    if (i == 0) g_off[N_NODES] = N_EDGES;
}

// ---------------- fill CSR (src + norm, sorted by dst) -----------------------------
__global__ void k_fill(const void* __restrict__ ei, const float* __restrict__ w) {
    int e = blockIdx.x * blockDim.x + threadIdx.x;
    if (e >= N_EDGES) return;
    int is64 = g_ei64;
    int s = load_idx(ei, e, is64, N_NODES);
    int d = load_idx(ei, (long long)N_EDGES + e, is64, N_NODES);
    int slot = g_off[d] + atomicAdd(&g_cur[d], 1);
    g_csr_src[slot]  = s;
    g_csr_norm[slot] = g_dis[s] * w[e] * g_dis[d];
}

// ---------------- GEMM: C[50000,96] = A @ W[96,96] -> g_xw -------------------------
// 32-row tile, 256 threads ALL computing (4 rows x 3 cols each). 48KB static smem.
__global__ void k_gemm(const float* __restrict__ Aext, int asel,
                       const float* __restrict__ W) {
    __shared__ float ws[96 * 96];                   // 36864 B
    __shared__ __align__(16) float xs[32 * 96];     // 12288 B  (total 49152 = 48KB)
    const float* A = (asel == 0) ? Aext : (asel == 1 ? g_hA : g_hB);
    float* C = g_xw;

    int tid = threadIdx.x;
    for (int idx = tid; idx < 96 * 96; idx += 256) ws[idx] = W[idx];

    int r0 = blockIdx.x * 32;
    const float4* A4 = (const float4*)A;
    float4* xs4 = (float4*)xs;
    for (int idx = tid; idx < 32 * 24; idx += 256) {
        int r = idx / 24;
        float4 v = make_float4(0.f, 0.f, 0.f, 0.f);
        if (r0 + r < N_NODES) v = A4[(size_t)r0 * 24 + idx];
        xs4[idx] = v;
    }
    __syncthreads();

    int tx = tid & 31, wy = tid >> 5;   // 8 warps x 4 rows = 32 rows
    int rb = wy * 4, c0 = tx * 3;

    float acc[4][3];
#pragma unroll
    for (int r = 0; r < 4; r++)
#pragma unroll
        for (int j = 0; j < 3; j++) acc[r][j] = 0.0f;

#pragma unroll 4
    for (int kk = 0; kk < 96; kk += 4) {
        float4 xv[4];
#pragma unroll
        for (int r = 0; r < 4; r++)
            xv[r] = *(const float4*)&xs[(rb + r) * 96 + kk];   // warp-broadcast
        float wv[4][3];
#pragma unroll
        for (int q = 0; q < 4; q++)
#pragma unroll
            for (int j = 0; j < 3; j++)
                wv[q][j] = ws[(kk + q) * 96 + c0 + j];
#pragma unroll
        for (int r = 0; r < 4; r++)
#pragma unroll
            for (int j = 0; j < 3; j++) {
                acc[r][j] = fmaf(xv[r].x, wv[0][j], acc[r][j]);
                acc[r][j] = fmaf(xv[r].y, wv[1][j], acc[r][j]);
                acc[r][j] = fmaf(xv[r].z, wv[2][j], acc[r][j]);
                acc[r][j] = fmaf(xv[r].w, wv[3][j], acc[r][j]);
            }
    }

#pragma unroll
    for (int r = 0; r < 4; r++) {
        int row = r0 + rb + r;
        if (row < N_NODES)
#pragma unroll
            for (int j = 0; j < 3; j++)
                C[(size_t)row * 96 + c0 + j] = acc[r][j];
    }
}

// ---------------- fused gather: CSR aggregate + self-loop + bias (+relu) (+pool) ---
// One warp per node. Lanes 0..23 each own one float4 of the 96-float row.
// 4x unrolled edge loop for deeper MLP.
__global__ void k_gather(int osel, const float* __restrict__ b, int relu, int do_pool) {
    int warp = (blockIdx.x * blockDim.x + threadIdx.x) >> 5;
    int lane = threadIdx.x & 31;
    if (warp >= N_NODES || lane >= NF4) return;
    float* out = buf_sel(osel);
    const float4* __restrict__ xw4 = (const float4*)g_xw;

    int beg = __ldg(&g_off[warp]), end = __ldg(&g_off[warp + 1]);
    float4 acc = make_float4(0.f, 0.f, 0.f, 0.f);
    int i = beg;
    for (; i + 3 < end; i += 4) {
        int   s0 = __ldg(&g_csr_src[i]),      s1 = __ldg(&g_csr_src[i + 1]);
        int   s2 = __ldg(&g_csr_src[i + 2]),  s3 = __ldg(&g_csr_src[i + 3]);
        float n0 = __ldg(&g_csr_norm[i]),     n1 = __ldg(&g_csr_norm[i + 1]);
        float n2 = __ldg(&g_csr_norm[i + 2]), n3 = __ldg(&g_csr_norm[i + 3]);
        float4 v0 = xw4[(size_t)s0 * NF4 + lane];
        float4 v1 = xw4[(size_t)s1 * NF4 + lane];
        float4 v2 = xw4[(size_t)s2 * NF4 + lane];
        float4 v3 = xw4[(size_t)s3 * NF4 + lane];
        acc.x = fmaf(n0, v0.x, acc.x); acc.y = fmaf(n0, v0.y, acc.y);
        acc.z = fmaf(n0, v0.z, acc.z); acc.w = fmaf(n0, v0.w, acc.w);
        acc.x = fmaf(n1, v1.x, acc.x); acc.y = fmaf(n1, v1.y, acc.y);
        acc.z = fmaf(n1, v1.z, acc.z); acc.w = fmaf(n1, v1.w, acc.w);
        acc.x = fmaf(n2, v2.x, acc.x); acc.y = fmaf(n2, v2.y, acc.y);
        acc.z = fmaf(n2, v2.z, acc.z); acc.w = fmaf(n2, v2.w, acc.w);
        acc.x = fmaf(n3, v3.x, acc.x); acc.y = fmaf(n3, v3.y, acc.y);
        acc.z = fmaf(n3, v3.z, acc.z); acc.w = fmaf(n3, v3.w, acc.w);
    }
    for (; i < end; i++) {
        int   s0 = __ldg(&g_csr_src[i]);
        float n0 = __ldg(&g_csr_norm[i]);
        float4 v0 = xw4[(size_t)s0 * NF4 + lane];
        acc.x = fmaf(n0, v0.x, acc.x); acc.y = fmaf(n0, v0.y, acc.y);
        acc.z = fmaf(n0, v0.z, acc.z); acc.w = fmaf(n0, v0.w, acc.w);
    }
    // self loop
    {
        float sn = g_selfn[warp];
        float4 v = xw4[(size_t)warp * NF4 + lane];
        acc.x = fmaf(sn, v.x, acc.x); acc.y = fmaf(sn, v.y, acc.y);
        acc.z = fmaf(sn, v.z, acc.z); acc.w = fmaf(sn, v.w, acc.w);
    }
    // bias + relu
    float4 bv = ((const float4*)b)[lane];
    acc.x += bv.x; acc.y += bv.y; acc.z += bv.z; acc.w += bv.w;
    if (relu) {
        acc.x = fmaxf(acc.x, 0.f); acc.y = fmaxf(acc.y, 0.f);
        acc.z = fmaxf(acc.z, 0.f); acc.w = fmaxf(acc.w, 0.f);
    }
    ((float4*)out)[(size_t)warp * NF4 + lane] = acc;

    if (do_pool) {
        int gph = g_gph[warp];
        float* pp = &g_pool[gph * F + lane * 4];
        atomicAdd(pp + 0, acc.x);
        atomicAdd(pp + 1, acc.y);
        atomicAdd(pp + 2, acc.z);
        atomicAdd(pp + 3, acc.w);
    }
}

// ---------------- head: out[g,c] = (pool[g,:]/cnt) @ Wl + bl -----------------------
__global__ void k_final(const float* __restrict__ Wl, const float* __restrict__ bl,
                        float* __restrict__ out) {
    int t = blockIdx.x * blockDim.x + threadIdx.x;
    if (t >= N_GRAPHS * N_CLASSES) return;
    int gph = t / N_CLASSES;
    int c = t - gph * N_CLASSES;
    float inv = 1.0f / fmaxf((float)g_cnt[gph], 1.0f);
    float s = 0.0f;
#pragma unroll 8
    for (int k = 0; k < 96; k++)
        s = fmaf(g_pool[gph * 96 + k], Wl[k * N_CLASSES + c], s);
    out[t] = s * inv + bl[c];
}

// ===================================================================================
extern "C" void kernel_launch(void* const* d_in, const int* in_sizes, int n_in,
                              void* d_out, int out_size) {
    // Identify inputs by element count; fall back to positional order.
    int ix = 0, iew = 1, iWl = 8, ibl = 9, iei = 10, ibatch = 11;
    int iW[3] = {2, 4, 6}, iB[3] = {3, 5, 7};
    {
        int tW[3], tB[3], nw = 0, nb = 0;
        int tx = -1, tew = -1, twl = -1, tbl = -1, tei = -1, tbt = -1;
        for (int i = 0; i < n_in; i++) {
            switch (in_sizes[i]) {
                case N_NODES * F:      tx  = i; break;
                case N_EDGES:          tew = i; break;
                case F * F:            if (nw < 3) tW[nw++] = i; break;
                case F:                if (nb < 3) tB[nb++] = i; break;
                case F * N_CLASSES:    twl = i; break;
                case N_CLASSES:        tbl = i; break;
                case 2 * N_EDGES:      tei = i; break;
                case N_NODES:          tbt = i; break;
                default: break;
            }
        }
        if (tx >= 0 && tew >= 0 && nw == 3 && nb == 3 && twl >= 0 && tbl >= 0 &&
            tei >= 0 && tbt >= 0) {
            ix = tx; iew = tew; iWl = twl; ibl = tbl; iei = tei; ibatch = tbt;
            for (int j = 0; j < 3; j++) { iW[j] = tW[j]; iB[j] = tB[j]; }
        }
    }

    const float* x     = (const float*)d_in[ix];
    const float* ew    = (const float*)d_in[iew];
    const float* W1    = (const float*)d_in[iW[0]];
    const float* b1    = (const float*)d_in[iB[0]];
    const float* W2    = (const float*)d_in[iW[1]];
    const float* b2    = (const float*)d_in[iB[1]];
    const float* W3    = (const float*)d_in[iW[2]];
    const float* b3    = (const float*)d_in[iB[2]];
    const float* Wl    = (const float*)d_in[iWl];
    const float* bl    = (const float*)d_in[ibl];
    const void*  ei    = d_in[iei];
    const void*  batch = d_in[ibatch];
    float* out = (float*)d_out;

    const int T = 256;
    const int node_grid = (N_NODES + T - 1) / T;
    const int edge_grid = (N_EDGES + T - 1) / T;

    // ---- prep: init+detect, degree, scan+dis, offsets, CSR fill ----
    k_init<<<node_grid, T>>>(ei, batch);
    k_prep<<<edge_grid, T>>>(ei, ew);
    k_scan1<<<SCAN_NB, 256>>>(batch);
    k_scan2<<<1, 256>>>();
    k_scan3<<<SCAN_NB, 256>>>();
    k_fill<<<edge_grid, T>>>(ei, ew);

    const int gemm_grid   = (N_NODES + 31) / 32;
    const int gather_grid = (N_NODES * 32 + T - 1) / T;   // one warp per node

    // ---- layer 1: x -> hA (relu) ----
    k_gemm<<<gemm_grid, T>>>(x, 0, W1);
    k_gather<<<gather_grid, T>>>(1, b1, 1, 0);

    // ---- layer 2: hA -> hB (relu) ----
    k_gemm<<<gemm_grid, T>>>(nullptr, 1, W2);
    k_gather<<<gather_grid, T>>>(2, b2, 1, 0);

    // ---- layer 3: hB -> hA (no relu) + fused mean-pool accumulation ----
    k_gemm<<<gemm_grid, T>>>(nullptr, 2, W3);
    k_gather<<<gather_grid, T>>>(1, b3, 0, 1);

    // ---- head ----
    k_final<<<(N_GRAPHS * N_CLASSES + T - 1) / T, T>>>(Wl, bl, out);
}

// round 10
// speedup vs baseline: 2.7998x; 1.1136x over previous
#include <cuda_runtime.h>
#include <cuda_fp16.h>
#include <cstdint>

#define N_NODES   50000
#define N_EDGES   800000
#define F         96
#define NF4       (F / 4)          // 24 float4 per node row
#define N_CLASSES 10
#define N_GRAPHS  512
#define NF        (N_NODES * F)
#define SCAN_NB   ((N_NODES + 255) / 256)   // 196

// ---------------- scratch (device globals; no allocations allowed) ----------------
__device__ float g_deg[N_NODES];
__device__ float g_dis[N_NODES];
__device__ float g_selfn[N_NODES];
__device__ int   g_gph[N_NODES];
__device__ int   g_cntd[N_NODES];
__device__ int   g_cur[N_NODES];
__device__ int   g_off[N_NODES + 1];
__device__ int   g_part[256];
__device__ int   g_partx[256];
__device__ int   g_csr_src[N_EDGES];
__device__ __align__(16) float  g_csr_norm[N_EDGES];
__device__ __align__(16) __half g_xwh[NF];          // fp16-staged GEMM output
__device__ __align__(16) float  g_hA[NF];
__device__ __align__(16) float  g_hB[NF];
__device__ float g_pool[N_GRAPHS * F];
__device__ int   g_cnt[N_GRAPHS];
__device__ int   g_ei64, g_b64;

__device__ __forceinline__ float* buf_sel(int s) { return s == 1 ? g_hA : g_hB; }

__device__ __forceinline__ int load_idx(const void* p, long long i, int is64, int lim) {
    long long v = is64 ? ((const long long*)p)[i] : (long long)((const int*)p)[i];
    int r = (int)v;
    if (r < 0) r = 0;
    if (r >= lim) r = lim - 1;
    return r;
}

// ---------------- init + dtype detection (merged) ----------------------------------
__global__ void k_init(const void* ei, const void* bt) {
    int i = blockIdx.x * blockDim.x + threadIdx.x;
    if (i < N_NODES) { g_deg[i] = 1.0f; g_cntd[i] = 0; g_cur[i] = 0; }
    if (i < N_GRAPHS * F)  g_pool[i] = 0.0f;
    if (i < N_GRAPHS)      g_cnt[i] = 0;
    if (i == 0) {
        const unsigned long long* p = (const unsigned long long*)ei;
        int is64 = 1;
        for (int k = 0; k < 512; k++)
            if (p[k] >= (1ULL << 32)) { is64 = 0; break; }
        g_ei64 = is64;
        const unsigned long long* q = (const unsigned long long*)bt;
        int b64 = 1;
        for (int k = 0; k < 512; k++)
            if (q[k] >= (1ULL << 32)) { b64 = 0; break; }
        g_b64 = b64;
    }
}

// ---------------- prep: weighted degree + dst counts ------------------------------
__global__ void k_prep(const void* __restrict__ ei, const float* __restrict__ w) {
    int e = blockIdx.x * blockDim.x + threadIdx.x;
    if (e >= N_EDGES) return;
    int is64 = g_ei64;
    int d = load_idx(ei, (long long)N_EDGES + e, is64, N_NODES);
    atomicAdd(&g_deg[d], w[e]);
    atomicAdd(&g_cntd[d], 1);
}

// ---------------- scan1 + dis + selfn + batch decode (merged) ----------------------
__global__ void k_scan1(const void* __restrict__ batch) {
    __shared__ int sm[256];
    int b = blockIdx.x, t = threadIdx.x;
    int i = b * 256 + t;

    if (i < N_NODES) {
        float dg  = g_deg[i];
        float dis = dg > 0.0f ? rsqrtf(dg) : 0.0f;
        g_dis[i]   = dis;
        g_selfn[i] = dis * dis;
        int gph = load_idx(batch, i, g_b64, N_GRAPHS);
        g_gph[i] = gph;
        // warp-aggregated count (batch is sorted; most warps share one gph)
        unsigned active = __activemask();
        unsigned mask = __match_any_sync(active, gph);
        int leader = __ffs(mask) - 1;
        if ((t & 31) == leader) atomicAdd(&g_cnt[gph], __popc(mask));
    }

    int v = (i < N_NODES) ? g_cntd[i] : 0;
    sm[t] = v; __syncthreads();
    for (int ofs = 1; ofs < 256; ofs <<= 1) {
        int add = (t >= ofs) ? sm[t - ofs] : 0;
        __syncthreads();
        sm[t] += add;
        __syncthreads();
    }
    if (i < N_NODES) g_off[i] = sm[t] - v;
    if (t == 255) g_part[b] = sm[255];
}

__global__ void k_scan2() {
    __shared__ int sm[256];
    int t = threadIdx.x;
    int v = (t < SCAN_NB) ? g_part[t] : 0;
    sm[t] = v; __syncthreads();
    for (int ofs = 1; ofs < 256; ofs <<= 1) {
        int add = (t >= ofs) ? sm[t - ofs] : 0;
        __syncthreads();
        sm[t] += add;
        __syncthreads();
    }
    g_partx[t] = sm[t] - v;
}

__global__ void k_scan3() {
    int i = blockIdx.x * 256 + threadIdx.x;
    if (i < N_NODES) g_off[i] += g_partx[blockIdx.x];
    if (i == 0) g_off[N_NODES] = N_EDGES;
}

// ---------------- fill CSR (src + norm, sorted by dst) -----------------------------
__global__ void k_fill(const void* __restrict__ ei, const float* __restrict__ w) {
    int e = blockIdx.x * blockDim.x + threadIdx.x;
    if (e >= N_EDGES) return;
    int is64 = g_ei64;
    int s = load_idx(ei, e, is64, N_NODES);
    int d = load_idx(ei, (long long)N_EDGES + e, is64, N_NODES);
    int slot = g_off[d] + atomicAdd(&g_cur[d], 1);
    g_csr_src[slot]  = s;
    g_csr_norm[slot] = g_dis[s] * w[e] * g_dis[d];
}

// ---------------- GEMM: g_xwh[50000,96] = A @ W[96,96]  (fp32 math, fp16 store) ----
__global__ void k_gemm(const float* __restrict__ Aext, int asel,
                       const float* __restrict__ W) {
    __shared__ float ws[96 * 96];                   // 36864 B
    __shared__ __align__(16) float xs[32 * 96];     // 12288 B (total 48 KB)
    const float* A = (asel == 0) ? Aext : (asel == 1 ? g_hA : g_hB);

    int tid = threadIdx.x;
    for (int idx = tid; idx < 96 * 96; idx += 256) ws[idx] = W[idx];

    int r0 = blockIdx.x * 32;
    const float4* A4 = (const float4*)A;
    float4* xs4 = (float4*)xs;
    for (int idx = tid; idx < 32 * 24; idx += 256) {
        int r = idx / 24;
        float4 v = make_float4(0.f, 0.f, 0.f, 0.f);
        if (r0 + r < N_NODES) v = A4[(size_t)r0 * 24 + idx];
        xs4[idx] = v;
    }
    __syncthreads();

    int tx = tid & 31, wy = tid >> 5;
    int rb = wy * 4, c0 = tx * 3;

    float acc[4][3];
#pragma unroll
    for (int r = 0; r < 4; r++)
#pragma unroll
        for (int j = 0; j < 3; j++) acc[r][j] = 0.0f;

#pragma unroll 4
    for (int kk = 0; kk < 96; kk += 4) {
        float4 xv[4];
#pragma unroll
        for (int r = 0; r < 4; r++)
            xv[r] = *(const float4*)&xs[(rb + r) * 96 + kk];
        float wv[4][3];
#pragma unroll
        for (int q = 0; q < 4; q++)
#pragma unroll
            for (int j = 0; j < 3; j++)
                wv[q][j] = ws[(kk + q) * 96 + c0 + j];
#pragma unroll
        for (int r = 0; r < 4; r++)
#pragma unroll
            for (int j = 0; j < 3; j++) {
                acc[r][j] = fmaf(xv[r].x, wv[0][j], acc[r][j]);
                acc[r][j] = fmaf(xv[r].y, wv[1][j], acc[r][j]);
                acc[r][j] = fmaf(xv[r].z, wv[2][j], acc[r][j]);
                acc[r][j] = fmaf(xv[r].w, wv[3][j], acc[r][j]);
            }
    }

#pragma unroll
    for (int r = 0; r < 4; r++) {
        int row = r0 + rb + r;
        if (row < N_NODES)
#pragma unroll
            for (int j = 0; j < 3; j++)
                g_xwh[(size_t)row * 96 + c0 + j] = __float2half_rn(acc[r][j]);
    }
}

// ---------------- fused gather: CSR aggregate + self-loop + bias (+relu) (+pool) ---
// One warp per node; lanes 0..23 each own 4 halves (8 B) of the 192 B fp16 row.
__global__ void k_gather(int osel, const float* __restrict__ bias, int relu, int do_pool) {
    int warp = (blockIdx.x * blockDim.x + threadIdx.x) >> 5;
    int lane = threadIdx.x & 31;
    if (warp >= N_NODES || lane >= NF4) return;
    float* out = buf_sel(osel);
    const uint2* __restrict__ xwu = (const uint2*)g_xwh;   // 24 uint2 per row

    int beg = __ldg(&g_off[warp]), end = __ldg(&g_off[warp + 1]);
    float4 acc = make_float4(0.f, 0.f, 0.f, 0.f);
    int i = beg;
    for (; i + 3 < end; i += 4) {
        int   s0 = __ldg(&g_csr_src[i]),      s1 = __ldg(&g_csr_src[i + 1]);
        int   s2 = __ldg(&g_csr_src[i + 2]),  s3 = __ldg(&g_csr_src[i + 3]);
        float n0 = __ldg(&g_csr_norm[i]),     n1 = __ldg(&g_csr_norm[i + 1]);
        float n2 = __ldg(&g_csr_norm[i + 2]), n3 = __ldg(&g_csr_norm[i + 3]);
        uint2 u0 = xwu[(size_t)s0 * NF4 + lane];
        uint2 u1 = xwu[(size_t)s1 * NF4 + lane];
        uint2 u2 = xwu[(size_t)s2 * NF4 + lane];
        uint2 u3 = xwu[(size_t)s3 * NF4 + lane];
        float2 lo0 = __half22float2(*(__half2*)&u0.x), hi0 = __half22float2(*(__half2*)&u0.y);
        float2 lo1 = __half22float2(*(__half2*)&u1.x), hi1 = __half22float2(*(__half2*)&u1.y);
        float2 lo2 = __half22float2(*(__half2*)&u2.x), hi2 = __half22float2(*(__half2*)&u2.y);
        float2 lo3 = __half22float2(*(__half2*)&u3.x), hi3 = __half22float2(*(__half2*)&u3.y);
        acc.x = fmaf(n0, lo0.x, acc.x); acc.y = fmaf(n0, lo0.y, acc.y);
        acc.z = fmaf(n0, hi0.x, acc.z); acc.w = fmaf(n0, hi0.y, acc.w);
        acc.x = fmaf(n1, lo1.x, acc.x); acc.y = fmaf(n1, lo1.y, acc.y);
        acc.z = fmaf(n1, hi1.x, acc.z); acc.w = fmaf(n1, hi1.y, acc.w);
        acc.x = fmaf(n2, lo2.x, acc.x); acc.y = fmaf(n2, lo2.y, acc.y);
        acc.z = fmaf(n2, hi2.x, acc.z); acc.w = fmaf(n2, hi2.y, acc.w);
        acc.x = fmaf(n3, lo3.x, acc.x); acc.y = fmaf(n3, lo3.y, acc.y);
        acc.z = fmaf(n3, hi3.x, acc.z); acc.w = fmaf(n3, hi3.y, acc.w);
    }
    for (; i < end; i++) {
        int   s0 = __ldg(&g_csr_src[i]);
        float n0 = __ldg(&g_csr_norm[i]);
        uint2 u0 = xwu[(size_t)s0 * NF4 + lane];
        float2 lo0 = __half22float2(*(__half2*)&u0.x), hi0 = __half22float2(*(__half2*)&u0.y);
        acc.x = fmaf(n0, lo0.x, acc.x); acc.y = fmaf(n0, lo0.y, acc.y);
        acc.z = fmaf(n0, hi0.x, acc.z); acc.w = fmaf(n0, hi0.y, acc.w);
    }
    // self loop
    {
        float sn = g_selfn[warp];
        uint2 u = xwu[(size_t)warp * NF4 + lane];
        float2 lo = __half22float2(*(__half2*)&u.x), hi = __half22float2(*(__half2*)&u.y);
        acc.x = fmaf(sn, lo.x, acc.x); acc.y = fmaf(sn, lo.y, acc.y);
        acc.z = fmaf(sn, hi.x, acc.z); acc.w = fmaf(sn, hi.y, acc.w);
    }
    // bias + relu
    float4 bv = ((const float4*)bias)[lane];
    acc.x += bv.x; acc.y += bv.y; acc.z += bv.z; acc.w += bv.w;
    if (relu) {
        acc.x = fmaxf(acc.x, 0.f); acc.y = fmaxf(acc.y, 0.f);
        acc.z = fmaxf(acc.z, 0.f); acc.w = fmaxf(acc.w, 0.f);
    }
    ((float4*)out)[(size_t)warp * NF4 + lane] = acc;

    if (do_pool) {
        int gph = g_gph[warp];
        float* pp = &g_pool[gph * F + lane * 4];
        atomicAdd(pp + 0, acc.x);
        atomicAdd(pp + 1, acc.y);
        atomicAdd(pp + 2, acc.z);
        atomicAdd(pp + 3, acc.w);
    }
}

// ---------------- head: out[g,c] = (pool[g,:]/cnt) @ Wl + bl -----------------------
__global__ void k_final(const float* __restrict__ Wl, const float* __restrict__ bl,
                        float* __restrict__ out) {
    int t = blockIdx.x * blockDim.x + threadIdx.x;
    if (t >= N_GRAPHS * N_CLASSES) return;
    int gph = t / N_CLASSES;
    int c = t - gph * N_CLASSES;
    float inv = 1.0f / fmaxf((float)g_cnt[gph], 1.0f);
    float s = 0.0f;
#pragma unroll 8
    for (int k = 0; k < 96; k++)
        s = fmaf(g_pool[gph * 96 + k], Wl[k * N_CLASSES + c], s);
    out[t] = s * inv + bl[c];
}

// ===================================================================================
extern "C" void kernel_launch(void* const* d_in, const int* in_sizes, int n_in,
                              void* d_out, int out_size) {
    int ix = 0, iew = 1, iWl = 8, ibl = 9, iei = 10, ibatch = 11;
    int iW[3] = {2, 4, 6}, iB[3] = {3, 5, 7};
    {
        int tW[3], tB[3], nw = 0, nb = 0;
        int tx = -1, tew = -1, twl = -1, tbl = -1, tei = -1, tbt = -1;
        for (int i = 0; i < n_in; i++) {
            switch (in_sizes[i]) {
                case N_NODES * F:      tx  = i; break;
                case N_EDGES:          tew = i; break;
                case F * F:            if (nw < 3) tW[nw++] = i; break;
                case F:                if (nb < 3) tB[nb++] = i; break;
                case F * N_CLASSES:    twl = i; break;
                case N_CLASSES:        tbl = i; break;
                case 2 * N_EDGES:      tei = i; break;
                case N_NODES:          tbt = i; break;
                default: break;
            }
        }
        if (tx >= 0 && tew >= 0 && nw == 3 && nb == 3 && twl >= 0 && tbl >= 0 &&
            tei >= 0 && tbt >= 0) {
            ix = tx; iew = tew; iWl = twl; ibl = tbl; iei = tei; ibatch = tbt;
            for (int j = 0; j < 3; j++) { iW[j] = tW[j]; iB[j] = tB[j]; }
        }
    }

    const float* x     = (const float*)d_in[ix];
    const float* ew    = (const float*)d_in[iew];
    const float* W1    = (const float*)d_in[iW[0]];
    const float* b1    = (const float*)d_in[iB[0]];
    const float* W2    = (const float*)d_in[iW[1]];
    const float* b2    = (const float*)d_in[iB[1]];
    const float* W3    = (const float*)d_in[iW[2]];
    const float* b3    = (const float*)d_in[iB[2]];
    const float* Wl    = (const float*)d_in[iWl];
    const float* bl    = (const float*)d_in[ibl];
    const void*  ei    = d_in[iei];
    const void*  batch = d_in[ibatch];
    float* out = (float*)d_out;

    const int T = 256;
    const int node_grid = (N_NODES + T - 1) / T;
    const int edge_grid = (N_EDGES + T - 1) / T;

    k_init<<<node_grid, T>>>(ei, batch);
    k_prep<<<edge_grid, T>>>(ei, ew);
    k_scan1<<<SCAN_NB, 256>>>(batch);
    k_scan2<<<1, 256>>>();
    k_scan3<<<SCAN_NB, 256>>>();
    k_fill<<<edge_grid, T>>>(ei, ew);

    const int gemm_grid   = (N_NODES + 31) / 32;
    const int gather_grid = (N_NODES * 32 + T - 1) / T;

    k_gemm<<<gemm_grid, T>>>(x, 0, W1);
    k_gather<<<gather_grid, T>>>(1, b1, 1, 0);

    k_gemm<<<gemm_grid, T>>>(nullptr, 1, W2);
    k_gather<<<gather_grid, T>>>(2, b2, 1, 0);

    k_gemm<<<gemm_grid, T>>>(nullptr, 2, W3);
    k_gather<<<gather_grid, T>>>(1, b3, 0, 1);

    k_final<<<(N_GRAPHS * N_CLASSES + T - 1) / T, T>>>(Wl, bl, out);
}

// round 11
// speedup vs baseline: 3.5983x; 1.2852x over previous
#include <cuda_runtime.h>
#include <cuda_fp16.h>
#include <cstdint>

#define N_NODES   50000
#define N_EDGES   800000
#define F         96
#define NF4       (F / 4)          // 24 float4 / uint2 per node row
#define N_CLASSES 10
#define N_GRAPHS  512
#define NF        (N_NODES * F)
#define SCAN_NB   ((N_NODES + 255) / 256)   // 196
#define WS_PITCH  104               // W smem pitch: 104 mod 32 = 8 -> conflict-free b-frags

// ---------------- scratch (device globals; no allocations allowed) ----------------
__device__ float g_deg[N_NODES];
__device__ float g_dis[N_NODES];
__device__ float g_selfn[N_NODES];
__device__ int   g_gph[N_NODES];
__device__ int   g_cntd[N_NODES];
__device__ int   g_cur[N_NODES];
__device__ int   g_off[N_NODES + 1];
__device__ int   g_part[256];
__device__ int   g_csr_src[N_EDGES];
__device__ __align__(16) float  g_csr_norm[N_EDGES];
__device__ __align__(16) __half g_xwh[NF];          // fp16-staged GEMM output
__device__ __align__(16) float  g_hA[NF];
__device__ __align__(16) float  g_hB[NF];
__device__ float g_pool[N_GRAPHS * F];
__device__ int   g_cnt[N_GRAPHS];
__device__ int   g_ei64, g_b64;

__device__ __forceinline__ float* buf_sel(int s) { return s == 1 ? g_hA : g_hB; }

__device__ __forceinline__ int load_idx(const void* p, long long i, int is64, int lim) {
    long long v = is64 ? ((const long long*)p)[i] : (long long)((const int*)p)[i];
    int r = (int)v;
    if (r < 0) r = 0;
    if (r >= lim) r = lim - 1;
    return r;
}

__device__ __forceinline__ unsigned f2tf32(float x) {
    unsigned u;
    asm("cvt.rna.tf32.f32 %0, %1;" : "=r"(u) : "f"(x));
    return u;
}

// ---------------- init + dtype detection (merged) ----------------------------------
__global__ void k_init(const void* ei, const void* bt) {
    int i = blockIdx.x * blockDim.x + threadIdx.x;
    if (i < N_NODES) { g_deg[i] = 1.0f; g_cntd[i] = 0; g_cur[i] = 0; }
    if (i < N_GRAPHS * F)  g_pool[i] = 0.0f;
    if (i < N_GRAPHS)      g_cnt[i] = 0;
    if (i == 0) {
        const unsigned long long* p = (const unsigned long long*)ei;
        int is64 = 1;
        for (int k = 0; k < 512; k++)
            if (p[k] >= (1ULL << 32)) { is64 = 0; break; }
        g_ei64 = is64;
        const unsigned long long* q = (const unsigned long long*)bt;
        int b64 = 1;
        for (int k = 0; k < 512; k++)
            if (q[k] >= (1ULL << 32)) { b64 = 0; break; }
        g_b64 = b64;
    }
}

// ---------------- prep: weighted degree + dst counts ------------------------------
__global__ void k_prep(const void* __restrict__ ei, const float* __restrict__ w) {
    int e = blockIdx.x * blockDim.x + threadIdx.x;
    if (e >= N_EDGES) return;
    int is64 = g_ei64;
    int d = load_idx(ei, (long long)N_EDGES + e, is64, N_NODES);
    atomicAdd(&g_deg[d], w[e]);
    atomicAdd(&g_cntd[d], 1);
}

// ---------------- scan1 + dis + selfn + batch decode (merged) ----------------------
__global__ void k_scan1(const void* __restrict__ batch) {
    __shared__ int sm[256];
    int b = blockIdx.x, t = threadIdx.x;
    int i = b * 256 + t;

    if (i < N_NODES) {
        float dg  = g_deg[i];
        float dis = dg > 0.0f ? rsqrtf(dg) : 0.0f;
        g_dis[i]   = dis;
        g_selfn[i] = dis * dis;
        int gph = load_idx(batch, i, g_b64, N_GRAPHS);
        g_gph[i] = gph;
        unsigned active = __activemask();
        unsigned mask = __match_any_sync(active, gph);
        int leader = __ffs(mask) - 1;
        if ((t & 31) == leader) atomicAdd(&g_cnt[gph], __popc(mask));
    }

    int v = (i < N_NODES) ? g_cntd[i] : 0;
    sm[t] = v; __syncthreads();
    for (int ofs = 1; ofs < 256; ofs <<= 1) {
        int add = (t >= ofs) ? sm[t - ofs] : 0;
        __syncthreads();
        sm[t] += add;
        __syncthreads();
    }
    if (i < N_NODES) g_off[i] = sm[t] - v;
    if (t == 255) g_part[b] = sm[255];
}

// ---------------- scan3: per-block prefix of partials + offset finalize ------------
__global__ void k_scan3() {
    __shared__ int sbase;
    int b = blockIdx.x, t = threadIdx.x;
    if (t < 32) {
        int s = 0;
        for (int j = t; j < b; j += 32) s += g_part[j];
#pragma unroll
        for (int o = 16; o > 0; o >>= 1) s += __shfl_down_sync(0xffffffff, s, o);
        if (t == 0) sbase = s;
    }
    __syncthreads();
    int i = b * 256 + t;
    if (i < N_NODES) g_off[i] += sbase;
    if (i == 0) g_off[N_NODES] = N_EDGES;
}

// ---------------- fill CSR (src + norm, sorted by dst) -----------------------------
__global__ void k_fill(const void* __restrict__ ei, const float* __restrict__ w) {
    int e = blockIdx.x * blockDim.x + threadIdx.x;
    if (e >= N_EDGES) return;
    int is64 = g_ei64;
    int s = load_idx(ei, e, is64, N_NODES);
    int d = load_idx(ei, (long long)N_EDGES + e, is64, N_NODES);
    int slot = g_off[d] + atomicAdd(&g_cur[d], 1);
    g_csr_src[slot]  = s;
    g_csr_norm[slot] = g_dis[s] * w[e] * g_dis[d];
}

// ---------------- GEMM (tensor path): g_xwh = A @ W, tf32 mma, fp32 accum ----------
// Block: 256 threads (8 warps), 128 rows. Warp: 16 rows x 96 cols via
// mma.sync.m16n8k8.tf32 (12 n-tiles x 12 k-steps). W in smem as tf32 bits,
// pitch 104 (8a+b bank mapping -> conflict-free).
__global__ void k_gemm(const float* __restrict__ Aext, int asel,
                       const float* __restrict__ W) {
    __shared__ unsigned ws[96 * WS_PITCH];          // 39936 B
    const float* A = (asel == 0) ? Aext : (asel == 1 ? g_hA : g_hB);

    int tid = threadIdx.x;
    for (int idx = tid; idx < 96 * 96; idx += 256) {
        int k = idx / 96, n = idx - k * 96;
        ws[k * WS_PITCH + n] = f2tf32(W[idx]);
    }
    __syncthreads();

    int lane = tid & 31, warp = tid >> 5;
    int r0 = blockIdx.x * 128 + warp * 16;
    int qr = lane >> 2;          // 0..7 row-within-group
    int qc = lane & 3;           // 0..3 col-within-group

    float acc[12][4];
#pragma unroll
    for (int n = 0; n < 12; n++)
#pragma unroll
        for (int j = 0; j < 4; j++) acc[n][j] = 0.0f;

    int row_lo = r0 + qr;
    int row_hi = row_lo + 8;
    int rl = row_lo < N_NODES ? row_lo : N_NODES - 1;
    int rh = row_hi < N_NODES ? row_hi : N_NODES - 1;

#pragma unroll
    for (int k0 = 0; k0 < 96; k0 += 8) {
        unsigned a0 = f2tf32(A[(size_t)rl * 96 + k0 + qc]);
        unsigned a1 = f2tf32(A[(size_t)rh * 96 + k0 + qc]);
        unsigned a2 = f2tf32(A[(size_t)rl * 96 + k0 + qc + 4]);
        unsigned a3 = f2tf32(A[(size_t)rh * 96 + k0 + qc + 4]);
#pragma unroll
        for (int n = 0; n < 12; n++) {
            unsigned b0 = ws[(k0 + qc) * WS_PITCH + n * 8 + qr];
            unsigned b1 = ws[(k0 + 4 + qc) * WS_PITCH + n * 8 + qr];
            asm volatile(
                "mma.sync.aligned.m16n8k8.row.col.f32.tf32.tf32.f32 "
                "{%0,%1,%2,%3}, {%4,%5,%6,%7}, {%8,%9}, {%0,%1,%2,%3};"
                : "+f"(acc[n][0]), "+f"(acc[n][1]), "+f"(acc[n][2]), "+f"(acc[n][3])
                : "r"(a0), "r"(a1), "r"(a2), "r"(a3), "r"(b0), "r"(b1));
        }
    }

    int colb = qc * 2;
#pragma unroll
    for (int n = 0; n < 12; n++) {
        int col = n * 8 + colb;
        if (row_lo < N_NODES)
            *(__half2*)&g_xwh[(size_t)row_lo * 96 + col] = __floats2half2_rn(acc[n][0], acc[n][1]);
        if (row_hi < N_NODES)
            *(__half2*)&g_xwh[(size_t)row_hi * 96 + col] = __floats2half2_rn(acc[n][2], acc[n][3]);
    }
}

// ---------------- fused gather: CSR aggregate + self-loop + bias (+relu) (+pool) ---
__global__ void k_gather(int osel, const float* __restrict__ bias, int relu, int do_pool) {
    int warp = (blockIdx.x * blockDim.x + threadIdx.x) >> 5;
    int lane = threadIdx.x & 31;
    if (warp >= N_NODES || lane >= NF4) return;
    float* out = buf_sel(osel);
    const uint2* __restrict__ xwu = (const uint2*)g_xwh;

    int beg = __ldg(&g_off[warp]), end = __ldg(&g_off[warp + 1]);
    float4 acc = make_float4(0.f, 0.f, 0.f, 0.f);
    int i = beg;
    for (; i + 3 < end; i += 4) {
        int   s0 = __ldg(&g_csr_src[i]),      s1 = __ldg(&g_csr_src[i + 1]);
        int   s2 = __ldg(&g_csr_src[i + 2]),  s3 = __ldg(&g_csr_src[i + 3]);
        float n0 = __ldg(&g_csr_norm[i]),     n1 = __ldg(&g_csr_norm[i + 1]);
        float n2 = __ldg(&g_csr_norm[i + 2]), n3 = __ldg(&g_csr_norm[i + 3]);
        uint2 u0 = xwu[(size_t)s0 * NF4 + lane];
        uint2 u1 = xwu[(size_t)s1 * NF4 + lane];
        uint2 u2 = xwu[(size_t)s2 * NF4 + lane];
        uint2 u3 = xwu[(size_t)s3 * NF4 + lane];
        float2 lo0 = __half22float2(*(__half2*)&u0.x), hi0 = __half22float2(*(__half2*)&u0.y);
        float2 lo1 = __half22float2(*(__half2*)&u1.x), hi1 = __half22float2(*(__half2*)&u1.y);
        float2 lo2 = __half22float2(*(__half2*)&u2.x), hi2 = __half22float2(*(__half2*)&u2.y);
        float2 lo3 = __half22float2(*(__half2*)&u3.x), hi3 = __half22float2(*(__half2*)&u3.y);
        acc.x = fmaf(n0, lo0.x, acc.x); acc.y = fmaf(n0, lo0.y, acc.y);
        acc.z = fmaf(n0, hi0.x, acc.z); acc.w = fmaf(n0, hi0.y, acc.w);
        acc.x = fmaf(n1, lo1.x, acc.x); acc.y = fmaf(n1, lo1.y, acc.y);
        acc.z = fmaf(n1, hi1.x, acc.z); acc.w = fmaf(n1, hi1.y, acc.w);
        acc.x = fmaf(n2, lo2.x, acc.x); acc.y = fmaf(n2, lo2.y, acc.y);
        acc.z = fmaf(n2, hi2.x, acc.z); acc.w = fmaf(n2, hi2.y, acc.w);
        acc.x = fmaf(n3, lo3.x, acc.x); acc.y = fmaf(n3, lo3.y, acc.y);
        acc.z = fmaf(n3, hi3.x, acc.z); acc.w = fmaf(n3, hi3.y, acc.w);
    }
    for (; i < end; i++) {
        int   s0 = __ldg(&g_csr_src[i]);
        float n0 = __ldg(&g_csr_norm[i]);
        uint2 u0 = xwu[(size_t)s0 * NF4 + lane];
        float2 lo0 = __half22float2(*(__half2*)&u0.x), hi0 = __half22float2(*(__half2*)&u0.y);
        acc.x = fmaf(n0, lo0.x, acc.x); acc.y = fmaf(n0, lo0.y, acc.y);
        acc.z = fmaf(n0, hi0.x, acc.z); acc.w = fmaf(n0, hi0.y, acc.w);
    }
    {
        float sn = g_selfn[warp];
        uint2 u = xwu[(size_t)warp * NF4 + lane];
        float2 lo = __half22float2(*(__half2*)&u.x), hi = __half22float2(*(__half2*)&u.y);
        acc.x = fmaf(sn, lo.x, acc.x); acc.y = fmaf(sn, lo.y, acc.y);
        acc.z = fmaf(sn, hi.x, acc.z); acc.w = fmaf(sn, hi.y, acc.w);
    }
    float4 bv = ((const float4*)bias)[lane];
    acc.x += bv.x; acc.y += bv.y; acc.z += bv.z; acc.w += bv.w;
    if (relu) {
        acc.x = fmaxf(acc.x, 0.f); acc.y = fmaxf(acc.y, 0.f);
        acc.z = fmaxf(acc.z, 0.f); acc.w = fmaxf(acc.w, 0.f);
    }
    ((float4*)out)[(size_t)warp * NF4 + lane] = acc;

    if (do_pool) {
        int gph = g_gph[warp];
        float* pp = &g_pool[gph * F + lane * 4];
        atomicAdd(pp + 0, acc.x);
        atomicAdd(pp + 1, acc.y);
        atomicAdd(pp + 2, acc.z);
        atomicAdd(pp + 3, acc.w);
    }
}

// ---------------- head: out[g,c] = (pool[g,:]/cnt) @ Wl + bl -----------------------
__global__ void k_final(const float* __restrict__ Wl, const float* __restrict__ bl,
                        float* __restrict__ out) {
    int t = blockIdx.x * blockDim.x + threadIdx.x;
    if (t >= N_GRAPHS * N_CLASSES) return;
    int gph = t / N_CLASSES;
    int c = t - gph * N_CLASSES;
    float inv = 1.0f / fmaxf((float)g_cnt[gph], 1.0f);
    float s = 0.0f;
#pragma unroll 8
    for (int k = 0; k < 96; k++)
        s = fmaf(g_pool[gph * 96 + k], Wl[k * N_CLASSES + c], s);
    out[t] = s * inv + bl[c];
}

// ===================================================================================
extern "C" void kernel_launch(void* const* d_in, const int* in_sizes, int n_in,
                              void* d_out, int out_size) {
    int ix = 0, iew = 1, iWl = 8, ibl = 9, iei = 10, ibatch = 11;
    int iW[3] = {2, 4, 6}, iB[3] = {3, 5, 7};
    {
        int tW[3], tB[3], nw = 0, nb = 0;
        int tx = -1, tew = -1, twl = -1, tbl = -1, tei = -1, tbt = -1;
        for (int i = 0; i < n_in; i++) {
            switch (in_sizes[i]) {
                case N_NODES * F:      tx  = i; break;
                case N_EDGES:          tew = i; break;
                case F * F:            if (nw < 3) tW[nw++] = i; break;
                case F:                if (nb < 3) tB[nb++] = i; break;
                case F * N_CLASSES:    twl = i; break;
                case N_CLASSES:        tbl = i; break;
                case 2 * N_EDGES:      tei = i; break;
                case N_NODES:          tbt = i; break;
                default: break;
            }
        }
        if (tx >= 0 && tew >= 0 && nw == 3 && nb == 3 && twl >= 0 && tbl >= 0 &&
            tei >= 0 && tbt >= 0) {
            ix = tx; iew = tew; iWl = twl; ibl = tbl; iei = tei; ibatch = tbt;
            for (int j = 0; j < 3; j++) { iW[j] = tW[j]; iB[j] = tB[j]; }
        }
    }

    const float* x     = (const float*)d_in[ix];
    const float* ew    = (const float*)d_in[iew];
    const float* W1    = (const float*)d_in[iW[0]];
    const float* b1    = (const float*)d_in[iB[0]];
    const float* W2    = (const float*)d_in[iW[1]];
    const float* b2    = (const float*)d_in[iB[1]];
    const float* W3    = (const float*)d_in[iW[2]];
    const float* b3    = (const float*)d_in[iB[2]];
    const float* Wl    = (const float*)d_in[iWl];
    const float* bl    = (const float*)d_in[ibl];
    const void*  ei    = d_in[iei];
    const void*  batch = d_in[ibatch];
    float* out = (float*)d_out;

    const int T = 256;
    const int node_grid = (N_NODES + T - 1) / T;
    const int edge_grid = (N_EDGES + T - 1) / T;

    k_init<<<node_grid, T>>>(ei, batch);
    k_prep<<<edge_grid, T>>>(ei, ew);
    k_scan1<<<SCAN_NB, 256>>>(batch);
    k_scan3<<<SCAN_NB, 256>>>();
    k_fill<<<edge_grid, T>>>(ei, ew);

    const int gemm_grid   = (N_NODES + 127) / 128;
    const int gather_grid = (N_NODES * 32 + T - 1) / T;

    k_gemm<<<gemm_grid, T>>>(x, 0, W1);
    k_gather<<<gather_grid, T>>>(1, b1, 1, 0);

    k_gemm<<<gemm_grid, T>>>(nullptr, 1, W2);
    k_gather<<<gather_grid, T>>>(2, b2, 1, 0);

    k_gemm<<<gemm_grid, T>>>(nullptr, 2, W3);
    k_gather<<<gather_grid, T>>>(1, b3, 0, 1);

    k_final<<<(N_GRAPHS * N_CLASSES + T - 1) / T, T>>>(Wl, bl, out);
}